// round 2
// baseline (speedup 1.0000x reference)
#include <cuda_runtime.h>
#include <cstdint>

#define N_SRC   200000
#define D       128
#define N_RULES 250000
#define PERIOD  8

// One warp per rule. lane l owns columns [4l, 4l+4).
__global__ __launch_bounds__(256, 8)
void weighted_rule_kernel(const float* __restrict__ layer_values,
                          const float* __restrict__ weights,
                          const int* __restrict__ indices,   // int32 (JAX x64 disabled)
                          float* __restrict__ out)
{
    const int warp_global = (blockIdx.x * blockDim.x + threadIdx.x) >> 5;
    if (warp_global >= N_RULES) return;
    const int lane = threadIdx.x & 31;

    const int* __restrict__ ip = indices + (size_t)warp_global * PERIOD;
    const float4* __restrict__ wrow =
        reinterpret_cast<const float4*>(weights + (size_t)warp_global * PERIOD * D);

    float4 acc = make_float4(0.f, 0.f, 0.f, 0.f);

#pragma unroll
    for (int p = 0; p < PERIOD; ++p) {
        const int src = ip[p];  // uniform within warp
        const float4 g = reinterpret_cast<const float4*>(
                             layer_values + (size_t)src * D)[lane];
        const float4 w = wrow[p * (D / 4) + lane];
        acc.x = fmaf(g.x, w.x, acc.x);
        acc.y = fmaf(g.y, w.y, acc.y);
        acc.z = fmaf(g.z, w.z, acc.z);
        acc.w = fmaf(g.w, w.w, acc.w);
    }

    float4 r;
    r.x = tanhf(acc.x);
    r.y = tanhf(acc.y);
    r.z = tanhf(acc.z);
    r.w = tanhf(acc.w);

    reinterpret_cast<float4*>(out + (size_t)warp_global * D)[lane] = r;
}

extern "C" void kernel_launch(void* const* d_in, const int* in_sizes, int n_in,
                              void* d_out, int out_size)
{
    // Identify inputs by element count (robust to metadata ordering):
    //   layer_values: 200000*128   = 25,600,000
    //   weights:      250000*8*128 = 256,000,000
    //   indices:      250000*8     = 2,000,000
    const float* lv  = nullptr;
    const float* w   = nullptr;
    const int*   idx = nullptr;
    for (int i = 0; i < n_in; ++i) {
        const long long sz = in_sizes[i];
        if (sz == (long long)N_SRC * D)                lv  = (const float*)d_in[i];
        else if (sz == (long long)N_RULES * PERIOD * D) w  = (const float*)d_in[i];
        else if (sz == (long long)N_RULES * PERIOD)    idx = (const int*)d_in[i];
    }

    float* out = (float*)d_out;  // [N_RULES, D] float32

    const int threads = 256;                 // 8 warps = 8 rules per block
    const int warps_per_block = threads / 32;
    const int blocks = (N_RULES + warps_per_block - 1) / warps_per_block;

    weighted_rule_kernel<<<blocks, threads>>>(lv, w, idx, out);
}

// round 7
// speedup vs baseline: 1.1866x; 1.1866x over previous
#include <cuda_runtime.h>
#include <cstdint>

#define N_SRC   200000
#define D       128
#define N_RULES 250000
#define PERIOD  8

// One warp per rule. lane l owns columns [4l, 4l+4).
// Cache strategy (intrinsics only, no inline PTX):
//   - weights: __ldcs  (1.02GB pure stream, never reused -> evict-first)
//   - output:  __stcs  (128MB streaming store)
//   - indices: __ldcs
//   - gather:  __ldg   (default; 102MB table should stay L2-resident once
//                       the streams are demoted)
__global__ __launch_bounds__(256, 8)
void weighted_rule_kernel(const float* __restrict__ layer_values,
                          const float* __restrict__ weights,
                          const int* __restrict__ indices,   // int32 (JAX x64 disabled)
                          float* __restrict__ out)
{
    const int warp_global = (blockIdx.x * blockDim.x + threadIdx.x) >> 5;
    if (warp_global >= N_RULES) return;
    const int lane = threadIdx.x & 31;

    const int*    ip   = indices + (size_t)warp_global * PERIOD;
    const float4* wrow = reinterpret_cast<const float4*>(
                             weights + (size_t)warp_global * PERIOD * D) + lane;

    // Prefetch all 8 indices up-front (uniform per warp).
    int src[PERIOD];
#pragma unroll
    for (int p = 0; p < PERIOD; ++p) src[p] = __ldcs(ip + p);

    float4 acc = make_float4(0.f, 0.f, 0.f, 0.f);

#pragma unroll
    for (int p = 0; p < PERIOD; ++p) {
        const float4 g = __ldg(reinterpret_cast<const float4*>(
                                   layer_values + (size_t)src[p] * D) + lane);
        const float4 w = __ldcs(wrow + p * (D / 4));
        acc.x = fmaf(g.x, w.x, acc.x);
        acc.y = fmaf(g.y, w.y, acc.y);
        acc.z = fmaf(g.z, w.z, acc.z);
        acc.w = fmaf(g.w, w.w, acc.w);
    }

    float4 r;
    r.x = tanhf(acc.x);
    r.y = tanhf(acc.y);
    r.z = tanhf(acc.z);
    r.w = tanhf(acc.w);

    __stcs(reinterpret_cast<float4*>(out + (size_t)warp_global * D) + lane, r);
}

extern "C" void kernel_launch(void* const* d_in, const int* in_sizes, int n_in,
                              void* d_out, int out_size)
{
    // Identify inputs by element count (robust to metadata ordering):
    const float* lv  = nullptr;
    const float* w   = nullptr;
    const int*   idx = nullptr;
    for (int i = 0; i < n_in; ++i) {
        const long long sz = in_sizes[i];
        if (sz == (long long)N_SRC * D)                 lv  = (const float*)d_in[i];
        else if (sz == (long long)N_RULES * PERIOD * D) w   = (const float*)d_in[i];
        else if (sz == (long long)N_RULES * PERIOD)     idx = (const int*)d_in[i];
    }

    float* out = (float*)d_out;  // [N_RULES, D] float32

    const int threads = 256;                 // 8 warps = 8 rules per block
    const int warps_per_block = threads / 32;
    const int blocks = (N_RULES + warps_per_block - 1) / warps_per_block;

    weighted_rule_kernel<<<blocks, threads>>>(lv, w, idx, out);
}